// round 14
// baseline (speedup 1.0000x reference)
#include <cuda_runtime.h>
#include <cstdint>

#define NN 100000
#define FF 32
#define DD 3
#define OO 32

// Module-load zero-initialized; the linear kernel re-zeroes after reading,
// so the accumulator is zero at the start of every kernel_launch invocation.
__device__ float g_accum[NN * FF];

// ---------------------------------------------------------------------------
// Edge kernel (R5/R7 hot loop, self-prepping prologue): 8 edges per
// warp-iteration, cooperative index/pseudo loads, SHFL distribution, two
// independent gather -> red.global.add.v4.f32 chains.
// ---------------------------------------------------------------------------
__global__ void __launch_bounds__(256) edge_kernel(
    const float* __restrict__ x,
    const int* __restrict__ ei32_,
    const float* __restrict__ pseudo,
    const float* __restrict__ mu,
    const float* __restrict__ sigma,
    int E) {
    const int lane  = threadIdx.x & 31;
    const int g     = lane >> 3;
    const int fbase = (lane & 7) * 4;
    const int warp  = (blockIdx.x * blockDim.x + threadIdx.x) >> 5;
    const int nwarps = (gridDim.x * blockDim.x) >> 5;
    const unsigned FULL = 0xffffffffu;

    const int* __restrict__ ei32 = ei32_;
    const long long* __restrict__ ei64 = (const long long*)ei32_;

    // dtype probe: if int64 little-endian (values < 2^31), the odd 32-bit
    // words are all zero. 32 lanes test the first 32 entries; ballot.
    int probe = ei32[2 * lane + 1];
    const int is64 = (__ballot_sync(FULL, probe != 0) == 0u);

    // self-prep: per-lane gaussian coefficients for its feature quad.
    // mu/sigma are 96 floats each -> L2-hot broadcast after first touch.
    float mu0[4], mu1[4], mu2[4], c0[4], c1[4], c2[4];
    const float kln = -0.5f * 1.4426950408889634f;
#pragma unroll
    for (int j = 0; j < 4; j++) {
        int f = fbase + j;
        mu0[j] = mu[f * DD + 0];
        mu1[j] = mu[f * DD + 1];
        mu2[j] = mu[f * DD + 2];
        float s0 = sigma[f * DD + 0];
        float s1 = sigma[f * DD + 1];
        float s2 = sigma[f * DD + 2];
        c0[j] = kln / (1e-14f + s0 * s0);
        c1[j] = kln / (1e-14f + s1 * s1);
        c2[j] = kln / (1e-14f + s2 * s2);
    }

    for (long long eb = (long long)warp * 8; eb < E; eb += (long long)nwarps * 8) {
        int idx = 0;
        {
            long long epos = eb + (lane & 7);
            if (lane < 16 && epos < E) {
                long long a = (lane < 8) ? epos : epos + (long long)E;
                idx = is64 ? (int)ei64[a] : ei32[a];
            }
        }
        float pv = 0.f;
        {
            long long ppos = eb * 3 + lane;
            if (lane < 24 && ppos < (long long)E * 3) pv = pseudo[ppos];
        }

        const int rA = __shfl_sync(FULL, idx, g);
        const int rB = __shfl_sync(FULL, idx, 4 + g);
        const int cA = __shfl_sync(FULL, idx, 8 + g);
        const int cB = __shfl_sync(FULL, idx, 12 + g);
        const float p0A = __shfl_sync(FULL, pv, 3 * g + 0);
        const float p1A = __shfl_sync(FULL, pv, 3 * g + 1);
        const float p2A = __shfl_sync(FULL, pv, 3 * g + 2);
        const float p0B = __shfl_sync(FULL, pv, 12 + 3 * g + 0);
        const float p1B = __shfl_sync(FULL, pv, 12 + 3 * g + 1);
        const float p2B = __shfl_sync(FULL, pv, 12 + 3 * g + 2);

        const bool aval = (eb + g) < E;
        const bool bval = (eb + 4 + g) < E;

        float4 xa = make_float4(0.f, 0.f, 0.f, 0.f);
        float4 xb = make_float4(0.f, 0.f, 0.f, 0.f);
        if (aval) xa = *reinterpret_cast<const float4*>(x + (size_t)cA * FF + fbase);
        if (bval) xb = *reinterpret_cast<const float4*>(x + (size_t)cB * FF + fbase);

        float xaj[4] = {xa.x, xa.y, xa.z, xa.w};
        float xbj[4] = {xb.x, xb.y, xb.z, xb.w};
        float vA[4], vB[4];
#pragma unroll
        for (int j = 0; j < 4; j++) {
            float d0 = p0A - mu0[j], d1 = p1A - mu1[j], d2 = p2A - mu2[j];
            float lw = d0 * d0 * c0[j] + d1 * d1 * c1[j] + d2 * d2 * c2[j];
            vA[j] = exp2f(lw) * xaj[j];
        }
#pragma unroll
        for (int j = 0; j < 4; j++) {
            float d0 = p0B - mu0[j], d1 = p1B - mu1[j], d2 = p2B - mu2[j];
            float lw = d0 * d0 * c0[j] + d1 * d1 * c1[j] + d2 * d2 * c2[j];
            vB[j] = exp2f(lw) * xbj[j];
        }

        if (aval) {
            float* dst = g_accum + (size_t)rA * FF + fbase;
            asm volatile("red.global.add.v4.f32 [%0], {%1, %2, %3, %4};"
                         :: "l"(dst), "f"(vA[0]), "f"(vA[1]), "f"(vA[2]), "f"(vA[3])
                         : "memory");
        }
        if (bval) {
            float* dst = g_accum + (size_t)rB * FF + fbase;
            asm volatile("red.global.add.v4.f32 [%0], {%1, %2, %3, %4};"
                         :: "l"(dst), "f"(vB[0]), "f"(vB[1]), "f"(vB[2]), "f"(vB[3])
                         : "memory");
        }
    }
}

// ---------------------------------------------------------------------------
// Linear epilogue (R7 winner + zero-after-read): 32-node warp tile, smem
// broadcast reads, W register-resident per lane. Each staged accum row is
// immediately re-zeroed so the next kernel_launch starts from zero.
// ---------------------------------------------------------------------------
__global__ void __launch_bounds__(256) linear_kernel(
    const float* __restrict__ W,
    const float* __restrict__ b,
    float* __restrict__ out,
    int N) {
    __shared__ float Ws[FF][FF + 1];
    __shared__ float bs[OO];
    __shared__ float As[8][32][36];

    const int tid = threadIdx.x;
    for (int i = tid; i < FF * OO; i += 256)
        Ws[i >> 5][i & 31] = W[i];
    if (tid < OO) bs[tid] = b[tid];
    __syncthreads();

    const int lane = tid & 31;
    const int w    = tid >> 5;

    float wreg[FF];
#pragma unroll
    for (int f = 0; f < FF; f++) wreg[f] = Ws[lane][f];
    const float bias = bs[lane];

    const int node0 = (blockIdx.x * 8 + w) * 32;
    if (node0 >= N) return;

    const float4 z4 = make_float4(0.f, 0.f, 0.f, 0.f);
#pragma unroll
    for (int r = 0; r < 8; r++) {
        int idx = r * 32 + lane;
        int n   = idx >> 3;
        int f4  = idx & 7;
        if (node0 + n < N) {
            float4* gp = reinterpret_cast<float4*>(g_accum + (size_t)(node0 + n) * FF + f4 * 4);
            float4 v = *gp;
            *gp = z4;                      // re-zero for next invocation
            *reinterpret_cast<float4*>(&As[w][n][f4 * 4]) = v;
        } else {
            *reinterpret_cast<float4*>(&As[w][n][f4 * 4]) = z4;
        }
    }
    __syncwarp();

    const int nmax = min(32, N - node0);
#pragma unroll 4
    for (int n = 0; n < 32; n++) {
        if (n >= nmax) break;
        float s0 = bias, s1 = 0.f, s2 = 0.f, s3 = 0.f;
#pragma unroll
        for (int f4 = 0; f4 < 8; f4++) {
            float4 a = *reinterpret_cast<const float4*>(&As[w][n][f4 * 4]);
            s0 += a.x * wreg[f4 * 4 + 0];
            s1 += a.y * wreg[f4 * 4 + 1];
            s2 += a.z * wreg[f4 * 4 + 2];
            s3 += a.w * wreg[f4 * 4 + 3];
        }
        out[(size_t)(node0 + n) * OO + lane] = (s0 + s1) + (s2 + s3);
    }
}

// ---------------------------------------------------------------------------
extern "C" void kernel_launch(void* const* d_in, const int* in_sizes, int n_in,
                              void* d_out, int out_size) {
    const float* x   = (const float*)d_in[0];
    const int*   ei  = (const int*)d_in[1];
    const float* ps  = (const float*)d_in[2];
    const float* mu  = (const float*)d_in[3];
    const float* sg  = (const float*)d_in[4];
    const float* W   = (const float*)d_in[5];
    const float* b   = (const float*)d_in[6];
    float*       out = (float*)d_out;

    const int E = in_sizes[1] / 2;
    const int N = in_sizes[0] / FF;

    edge_kernel<<<148 * 8, 256>>>(x, ei, ps, mu, sg, E);
    linear_kernel<<<(N + 255) / 256, 256>>>(W, b, out, N);
}

// round 15
// speedup vs baseline: 1.1656x; 1.1656x over previous
#include <cuda_runtime.h>
#include <cstdint>

#define NN 100000
#define FF 32
#define DD 3
#define OO 32

__device__ float g_accum[NN * FF];
__device__ float g_mu_t[DD * FF];   // [d][f]
__device__ float g_c_t[DD * FF];    // [d][f] = -0.5*log2(e)/(1e-14+sigma^2)
__device__ int   g_is64;

// ---------------------------------------------------------------------------
// Merged zero + prep: ONE float4 store per thread (grid sized exactly),
// block 0 additionally transposes params + parallel dtype probe.
// ---------------------------------------------------------------------------
__global__ void prep_zero_kernel(const float* __restrict__ mu,
                                 const float* __restrict__ sigma,
                                 const int* __restrict__ ei32,
                                 int total_elems) {
    const int i = blockIdx.x * blockDim.x + threadIdx.x;   // 0 .. 799999
    reinterpret_cast<float4*>(g_accum)[i] = make_float4(0.f, 0.f, 0.f, 0.f);

    if (blockIdx.x == 0) {
        __shared__ int s_nz;
        int t = threadIdx.x;
        if (t == 0) s_nz = 0;
        __syncthreads();

        if (t < DD * FF) {
            int d = t / FF;
            int f = t % FF;
            float m = mu[f * DD + d];
            float s = sigma[f * DD + d];
            g_mu_t[d * FF + f] = m;
            g_c_t[d * FF + f]  = -0.5f * 1.4426950408889634f / (1e-14f + s * s);
        }

        // parallel probe: int64 little-endian (values < 2^31) => every odd
        // 32-bit word is zero. 256 threads each test one odd word.
        {
            int limit = 2 * total_elems;
            int widx = 2 * t + 1;
            int v = (widx < limit) ? ei32[widx] : 0;
            if (v != 0) atomicAdd(&s_nz, 1);
        }
        __syncthreads();
        if (t == 0) g_is64 = (s_nz == 0);
    }
}

// ---------------------------------------------------------------------------
// Edge kernel (R5/R7 winner, byte-identical): 8 edges per warp-iteration,
// cooperative index/pseudo loads, SHFL distribution, two independent
// gather -> red.global.add.v4.f32 chains.
// ---------------------------------------------------------------------------
__global__ void __launch_bounds__(256) edge_kernel(
    const float* __restrict__ x,
    const void* __restrict__ edge_index,
    const float* __restrict__ pseudo,
    int E) {
    const int lane  = threadIdx.x & 31;
    const int g     = lane >> 3;
    const int fbase = (lane & 7) * 4;
    const int warp  = (blockIdx.x * blockDim.x + threadIdx.x) >> 5;
    const int nwarps = (gridDim.x * blockDim.x) >> 5;
    const unsigned FULL = 0xffffffffu;

    const int is64 = g_is64;
    const int* __restrict__ ei32 = (const int*)edge_index;
    const long long* __restrict__ ei64 = (const long long*)edge_index;

    float mu0[4], mu1[4], mu2[4], c0[4], c1[4], c2[4];
#pragma unroll
    for (int j = 0; j < 4; j++) {
        mu0[j] = g_mu_t[0 * FF + fbase + j];
        mu1[j] = g_mu_t[1 * FF + fbase + j];
        mu2[j] = g_mu_t[2 * FF + fbase + j];
        c0[j]  = g_c_t[0 * FF + fbase + j];
        c1[j]  = g_c_t[1 * FF + fbase + j];
        c2[j]  = g_c_t[2 * FF + fbase + j];
    }

    for (long long eb = (long long)warp * 8; eb < E; eb += (long long)nwarps * 8) {
        int idx = 0;
        {
            long long epos = eb + (lane & 7);
            if (lane < 16 && epos < E) {
                long long a = (lane < 8) ? epos : epos + (long long)E;
                idx = is64 ? (int)ei64[a] : ei32[a];
            }
        }
        float pv = 0.f;
        {
            long long ppos = eb * 3 + lane;
            if (lane < 24 && ppos < (long long)E * 3) pv = pseudo[ppos];
        }

        const int rA = __shfl_sync(FULL, idx, g);
        const int rB = __shfl_sync(FULL, idx, 4 + g);
        const int cA = __shfl_sync(FULL, idx, 8 + g);
        const int cB = __shfl_sync(FULL, idx, 12 + g);
        const float p0A = __shfl_sync(FULL, pv, 3 * g + 0);
        const float p1A = __shfl_sync(FULL, pv, 3 * g + 1);
        const float p2A = __shfl_sync(FULL, pv, 3 * g + 2);
        const float p0B = __shfl_sync(FULL, pv, 12 + 3 * g + 0);
        const float p1B = __shfl_sync(FULL, pv, 12 + 3 * g + 1);
        const float p2B = __shfl_sync(FULL, pv, 12 + 3 * g + 2);

        const bool aval = (eb + g) < E;
        const bool bval = (eb + 4 + g) < E;

        float4 xa = make_float4(0.f, 0.f, 0.f, 0.f);
        float4 xb = make_float4(0.f, 0.f, 0.f, 0.f);
        if (aval) xa = *reinterpret_cast<const float4*>(x + (size_t)cA * FF + fbase);
        if (bval) xb = *reinterpret_cast<const float4*>(x + (size_t)cB * FF + fbase);

        float xaj[4] = {xa.x, xa.y, xa.z, xa.w};
        float xbj[4] = {xb.x, xb.y, xb.z, xb.w};
        float vA[4], vB[4];
#pragma unroll
        for (int j = 0; j < 4; j++) {
            float d0 = p0A - mu0[j], d1 = p1A - mu1[j], d2 = p2A - mu2[j];
            float lw = d0 * d0 * c0[j] + d1 * d1 * c1[j] + d2 * d2 * c2[j];
            vA[j] = exp2f(lw) * xaj[j];
        }
#pragma unroll
        for (int j = 0; j < 4; j++) {
            float d0 = p0B - mu0[j], d1 = p1B - mu1[j], d2 = p2B - mu2[j];
            float lw = d0 * d0 * c0[j] + d1 * d1 * c1[j] + d2 * d2 * c2[j];
            vB[j] = exp2f(lw) * xbj[j];
        }

        if (aval) {
            float* dst = g_accum + (size_t)rA * FF + fbase;
            asm volatile("red.global.add.v4.f32 [%0], {%1, %2, %3, %4};"
                         :: "l"(dst), "f"(vA[0]), "f"(vA[1]), "f"(vA[2]), "f"(vA[3])
                         : "memory");
        }
        if (bval) {
            float* dst = g_accum + (size_t)rB * FF + fbase;
            asm volatile("red.global.add.v4.f32 [%0], {%1, %2, %3, %4};"
                         :: "l"(dst), "f"(vB[0]), "f"(vB[1]), "f"(vB[2]), "f"(vB[3])
                         : "memory");
        }
    }
}

// ---------------------------------------------------------------------------
// Linear epilogue (R7 winner, byte-identical): 32-node warp tile, smem
// broadcast reads, W register-resident per lane.
// ---------------------------------------------------------------------------
__global__ void __launch_bounds__(256) linear_kernel(
    const float* __restrict__ W,
    const float* __restrict__ b,
    float* __restrict__ out,
    int N) {
    __shared__ float Ws[FF][FF + 1];
    __shared__ float bs[OO];
    __shared__ float As[8][32][36];

    const int tid = threadIdx.x;
    for (int i = tid; i < FF * OO; i += 256)
        Ws[i >> 5][i & 31] = W[i];
    if (tid < OO) bs[tid] = b[tid];
    __syncthreads();

    const int lane = tid & 31;
    const int w    = tid >> 5;

    float wreg[FF];
#pragma unroll
    for (int f = 0; f < FF; f++) wreg[f] = Ws[lane][f];
    const float bias = bs[lane];

    const int node0 = (blockIdx.x * 8 + w) * 32;
    if (node0 >= N) return;

#pragma unroll
    for (int r = 0; r < 8; r++) {
        int idx = r * 32 + lane;
        int n   = idx >> 3;
        int f4  = idx & 7;
        float4 v = make_float4(0.f, 0.f, 0.f, 0.f);
        if (node0 + n < N)
            v = *reinterpret_cast<const float4*>(g_accum + (size_t)(node0 + n) * FF + f4 * 4);
        *reinterpret_cast<float4*>(&As[w][n][f4 * 4]) = v;
    }
    __syncwarp();

    const int nmax = min(32, N - node0);
#pragma unroll 4
    for (int n = 0; n < 32; n++) {
        if (n >= nmax) break;
        float s0 = bias, s1 = 0.f, s2 = 0.f, s3 = 0.f;
#pragma unroll
        for (int f4 = 0; f4 < 8; f4++) {
            float4 a = *reinterpret_cast<const float4*>(&As[w][n][f4 * 4]);
            s0 += a.x * wreg[f4 * 4 + 0];
            s1 += a.y * wreg[f4 * 4 + 1];
            s2 += a.z * wreg[f4 * 4 + 2];
            s3 += a.w * wreg[f4 * 4 + 3];
        }
        out[(size_t)(node0 + n) * OO + lane] = (s0 + s1) + (s2 + s3);
    }
}

// ---------------------------------------------------------------------------
extern "C" void kernel_launch(void* const* d_in, const int* in_sizes, int n_in,
                              void* d_out, int out_size) {
    const float* x   = (const float*)d_in[0];
    const void*  ei  = d_in[1];
    const float* ps  = (const float*)d_in[2];
    const float* mu  = (const float*)d_in[3];
    const float* sg  = (const float*)d_in[4];
    const float* W   = (const float*)d_in[5];
    const float* b   = (const float*)d_in[6];
    float*       out = (float*)d_out;

    const int E = in_sizes[1] / 2;
    const int N = in_sizes[0] / FF;

    // (NN*FF/4) / 256 = 3125 blocks: exactly one float4 store per thread
    prep_zero_kernel<<<3125, 256>>>(mu, sg, (const int*)ei, in_sizes[1]);
    edge_kernel<<<148 * 8, 256>>>(x, ei, ps, E);
    linear_kernel<<<(N + 255) / 256, 256>>>(W, b, out, N);
}

// round 16
// speedup vs baseline: 1.1698x; 1.0035x over previous
#include <cuda_runtime.h>
#include <cstdint>

#define NN 100000
#define FF 32
#define DD 3
#define OO 32

__device__ float g_accum[NN * FF];
__device__ float g_mu_t[DD * FF];   // [d][f]
__device__ float g_c_t[DD * FF];    // [d][f] = -0.5*log2(e)/(1e-14+sigma^2)
__device__ int   g_is64;

// ---------------------------------------------------------------------------
// Merged zero + prep: ONE guarded float4 store per thread, 1024-thread
// blocks (782 blocks -> ~5 dispatch waves instead of 21). Block 0 also
// transposes params + parallel dtype probe.
// ---------------------------------------------------------------------------
__global__ void __launch_bounds__(1024) prep_zero_kernel(
    const float* __restrict__ mu,
    const float* __restrict__ sigma,
    const int* __restrict__ ei32,
    int total_elems) {
    const int i = blockIdx.x * blockDim.x + threadIdx.x;
    if (i < (NN * FF) / 4)
        reinterpret_cast<float4*>(g_accum)[i] = make_float4(0.f, 0.f, 0.f, 0.f);

    if (blockIdx.x == 0) {
        __shared__ int s_nz;
        int t = threadIdx.x;
        if (t == 0) s_nz = 0;
        __syncthreads();

        if (t < DD * FF) {
            int d = t / FF;
            int f = t % FF;
            float m = mu[f * DD + d];
            float s = sigma[f * DD + d];
            g_mu_t[d * FF + f] = m;
            g_c_t[d * FF + f]  = -0.5f * 1.4426950408889634f / (1e-14f + s * s);
        }

        // parallel probe: int64 little-endian (values < 2^31) => every odd
        // 32-bit word is zero. 1024 threads each test one odd word.
        {
            int limit = 2 * total_elems;
            int widx = 2 * t + 1;
            int v = (widx < limit) ? ei32[widx] : 0;
            if (v != 0) atomicAdd(&s_nz, 1);
        }
        __syncthreads();
        if (t == 0) g_is64 = (s_nz == 0);
    }
}

// ---------------------------------------------------------------------------
// Edge kernel (R5/R7 winner, byte-identical): 8 edges per warp-iteration,
// cooperative index/pseudo loads, SHFL distribution, two independent
// gather -> red.global.add.v4.f32 chains.
// ---------------------------------------------------------------------------
__global__ void __launch_bounds__(256) edge_kernel(
    const float* __restrict__ x,
    const void* __restrict__ edge_index,
    const float* __restrict__ pseudo,
    int E) {
    const int lane  = threadIdx.x & 31;
    const int g     = lane >> 3;
    const int fbase = (lane & 7) * 4;
    const int warp  = (blockIdx.x * blockDim.x + threadIdx.x) >> 5;
    const int nwarps = (gridDim.x * blockDim.x) >> 5;
    const unsigned FULL = 0xffffffffu;

    const int is64 = g_is64;
    const int* __restrict__ ei32 = (const int*)edge_index;
    const long long* __restrict__ ei64 = (const long long*)edge_index;

    float mu0[4], mu1[4], mu2[4], c0[4], c1[4], c2[4];
#pragma unroll
    for (int j = 0; j < 4; j++) {
        mu0[j] = g_mu_t[0 * FF + fbase + j];
        mu1[j] = g_mu_t[1 * FF + fbase + j];
        mu2[j] = g_mu_t[2 * FF + fbase + j];
        c0[j]  = g_c_t[0 * FF + fbase + j];
        c1[j]  = g_c_t[1 * FF + fbase + j];
        c2[j]  = g_c_t[2 * FF + fbase + j];
    }

    for (long long eb = (long long)warp * 8; eb < E; eb += (long long)nwarps * 8) {
        int idx = 0;
        {
            long long epos = eb + (lane & 7);
            if (lane < 16 && epos < E) {
                long long a = (lane < 8) ? epos : epos + (long long)E;
                idx = is64 ? (int)ei64[a] : ei32[a];
            }
        }
        float pv = 0.f;
        {
            long long ppos = eb * 3 + lane;
            if (lane < 24 && ppos < (long long)E * 3) pv = pseudo[ppos];
        }

        const int rA = __shfl_sync(FULL, idx, g);
        const int rB = __shfl_sync(FULL, idx, 4 + g);
        const int cA = __shfl_sync(FULL, idx, 8 + g);
        const int cB = __shfl_sync(FULL, idx, 12 + g);
        const float p0A = __shfl_sync(FULL, pv, 3 * g + 0);
        const float p1A = __shfl_sync(FULL, pv, 3 * g + 1);
        const float p2A = __shfl_sync(FULL, pv, 3 * g + 2);
        const float p0B = __shfl_sync(FULL, pv, 12 + 3 * g + 0);
        const float p1B = __shfl_sync(FULL, pv, 12 + 3 * g + 1);
        const float p2B = __shfl_sync(FULL, pv, 12 + 3 * g + 2);

        const bool aval = (eb + g) < E;
        const bool bval = (eb + 4 + g) < E;

        float4 xa = make_float4(0.f, 0.f, 0.f, 0.f);
        float4 xb = make_float4(0.f, 0.f, 0.f, 0.f);
        if (aval) xa = *reinterpret_cast<const float4*>(x + (size_t)cA * FF + fbase);
        if (bval) xb = *reinterpret_cast<const float4*>(x + (size_t)cB * FF + fbase);

        float xaj[4] = {xa.x, xa.y, xa.z, xa.w};
        float xbj[4] = {xb.x, xb.y, xb.z, xb.w};
        float vA[4], vB[4];
#pragma unroll
        for (int j = 0; j < 4; j++) {
            float d0 = p0A - mu0[j], d1 = p1A - mu1[j], d2 = p2A - mu2[j];
            float lw = d0 * d0 * c0[j] + d1 * d1 * c1[j] + d2 * d2 * c2[j];
            vA[j] = exp2f(lw) * xaj[j];
        }
#pragma unroll
        for (int j = 0; j < 4; j++) {
            float d0 = p0B - mu0[j], d1 = p1B - mu1[j], d2 = p2B - mu2[j];
            float lw = d0 * d0 * c0[j] + d1 * d1 * c1[j] + d2 * d2 * c2[j];
            vB[j] = exp2f(lw) * xbj[j];
        }

        if (aval) {
            float* dst = g_accum + (size_t)rA * FF + fbase;
            asm volatile("red.global.add.v4.f32 [%0], {%1, %2, %3, %4};"
                         :: "l"(dst), "f"(vA[0]), "f"(vA[1]), "f"(vA[2]), "f"(vA[3])
                         : "memory");
        }
        if (bval) {
            float* dst = g_accum + (size_t)rB * FF + fbase;
            asm volatile("red.global.add.v4.f32 [%0], {%1, %2, %3, %4};"
                         :: "l"(dst), "f"(vB[0]), "f"(vB[1]), "f"(vB[2]), "f"(vB[3])
                         : "memory");
        }
    }
}

// ---------------------------------------------------------------------------
// Linear epilogue (R7 winner, byte-identical): 32-node warp tile, smem
// broadcast reads, W register-resident per lane.
// ---------------------------------------------------------------------------
__global__ void __launch_bounds__(256) linear_kernel(
    const float* __restrict__ W,
    const float* __restrict__ b,
    float* __restrict__ out,
    int N) {
    __shared__ float Ws[FF][FF + 1];
    __shared__ float bs[OO];
    __shared__ float As[8][32][36];

    const int tid = threadIdx.x;
    for (int i = tid; i < FF * OO; i += 256)
        Ws[i >> 5][i & 31] = W[i];
    if (tid < OO) bs[tid] = b[tid];
    __syncthreads();

    const int lane = tid & 31;
    const int w    = tid >> 5;

    float wreg[FF];
#pragma unroll
    for (int f = 0; f < FF; f++) wreg[f] = Ws[lane][f];
    const float bias = bs[lane];

    const int node0 = (blockIdx.x * 8 + w) * 32;
    if (node0 >= N) return;

#pragma unroll
    for (int r = 0; r < 8; r++) {
        int idx = r * 32 + lane;
        int n   = idx >> 3;
        int f4  = idx & 7;
        float4 v = make_float4(0.f, 0.f, 0.f, 0.f);
        if (node0 + n < N)
            v = *reinterpret_cast<const float4*>(g_accum + (size_t)(node0 + n) * FF + f4 * 4);
        *reinterpret_cast<float4*>(&As[w][n][f4 * 4]) = v;
    }
    __syncwarp();

    const int nmax = min(32, N - node0);
#pragma unroll 4
    for (int n = 0; n < 32; n++) {
        if (n >= nmax) break;
        float s0 = bias, s1 = 0.f, s2 = 0.f, s3 = 0.f;
#pragma unroll
        for (int f4 = 0; f4 < 8; f4++) {
            float4 a = *reinterpret_cast<const float4*>(&As[w][n][f4 * 4]);
            s0 += a.x * wreg[f4 * 4 + 0];
            s1 += a.y * wreg[f4 * 4 + 1];
            s2 += a.z * wreg[f4 * 4 + 2];
            s3 += a.w * wreg[f4 * 4 + 3];
        }
        out[(size_t)(node0 + n) * OO + lane] = (s0 + s1) + (s2 + s3);
    }
}

// ---------------------------------------------------------------------------
extern "C" void kernel_launch(void* const* d_in, const int* in_sizes, int n_in,
                              void* d_out, int out_size) {
    const float* x   = (const float*)d_in[0];
    const void*  ei  = d_in[1];
    const float* ps  = (const float*)d_in[2];
    const float* mu  = (const float*)d_in[3];
    const float* sg  = (const float*)d_in[4];
    const float* W   = (const float*)d_in[5];
    const float* b   = (const float*)d_in[6];
    float*       out = (float*)d_out;

    const int E = in_sizes[1] / 2;
    const int N = in_sizes[0] / FF;

    // ceil(800000 / 1024) = 782 blocks, one guarded float4 store per thread
    prep_zero_kernel<<<782, 1024>>>(mu, sg, (const int*)ei, in_sizes[1]);
    edge_kernel<<<148 * 8, 256>>>(x, ei, ps, E);
    linear_kernel<<<(N + 255) / 256, 256>>>(W, b, out, N);
}